// round 12
// baseline (speedup 1.0000x reference)
#include <cuda_runtime.h>
#include <cooperative_groups.h>
#include <cstdint>

namespace cg = cooperative_groups;

#define MARGIN 1.0f
#define MAX_TRIALS 50
#define BLK 256
#define EPB 1024                           // elements per block (256 threads x 4)
#define MAX_B (1 << 20)
#define MAX_NB (MAX_B / EPB)               // 1024

// Scratch (no allocations allowed in kernel_launch)
__device__ float g_neg_score[MAX_B];   // scores of label-0 examples, stable order
__device__ float g_pos_score[MAX_B];   // scores of label-1 examples, stable order
__device__ int   g_pos_idx[MAX_B];     // original indices of label-1 examples
__device__ int   g_blockcnt[MAX_NB];
__device__ float g_extra;
__device__ float g_harm[MAX_TRIALS];

// ---------------- Threefry-2x32 (exact JAX partitionable semantics) --------
__device__ __forceinline__ uint32_t rotl32(uint32_t x, int d) {
    return __funnelshift_l(x, x, d);
}

__device__ __forceinline__ uint32_t jax_random_bits32(uint32_t j) {
    const uint32_t k0 = 0u, k1 = 42u;
    const uint32_t ks2 = k0 ^ k1 ^ 0x1BD11BDAu;
    uint32_t x0 = 0u + k0;          // c0 = hi32(j) = 0
    uint32_t x1 = j + k1;           // c1 = lo32(j)
    const int R0[4] = {13, 15, 26, 6};
    const int R1[4] = {17, 29, 16, 24};
#pragma unroll
    for (int i = 0; i < 4; i++) { x0 += x1; x1 = rotl32(x1, R0[i]); x1 ^= x0; }
    x0 += k1;  x1 += ks2 + 1u;
#pragma unroll
    for (int i = 0; i < 4; i++) { x0 += x1; x1 = rotl32(x1, R1[i]); x1 ^= x0; }
    x0 += ks2; x1 += k0 + 2u;
#pragma unroll
    for (int i = 0; i < 4; i++) { x0 += x1; x1 = rotl32(x1, R0[i]); x1 ^= x0; }
    x0 += k0;  x1 += k1 + 3u;
#pragma unroll
    for (int i = 0; i < 4; i++) { x0 += x1; x1 = rotl32(x1, R1[i]); x1 ^= x0; }
    x0 += k1;  x1 += ks2 + 4u;
#pragma unroll
    for (int i = 0; i < 4; i++) { x0 += x1; x1 = rotl32(x1, R0[i]); x1 ^= x0; }
    x0 += ks2; x1 += k0 + 5u;
    return x0 ^ x1;
}

__device__ __forceinline__ float bits_to_uniform(uint32_t bits) {
    return __uint_as_float((bits >> 9) | 0x3f800000u) - 1.0f;
}

__device__ __forceinline__ float sample_neg(uint32_t j, float nnf, int num_neg) {
    float u = bits_to_uniform(jax_random_bits32(j));
    int idx = (int)(u * nnf);
    idx = min(max(idx, 0), num_neg - 1);
    return __ldg(&g_neg_score[idx]);
}

// ---------------- ONE cooperative kernel: count | scatter | loss -----------
__global__ __launch_bounds__(BLK, 8)
void everything_kernel(const int* __restrict__ labels,
                       const float* __restrict__ scores,
                       float* __restrict__ out, int B, int nb) {
    cg::grid_group grid = cg::this_grid();
    __shared__ int   wtot[BLK / 32];
    __shared__ int   woff[BLK / 32];
    __shared__ int   redi[BLK];
    __shared__ int   redt[BLK];
    __shared__ int   hq[1024];
    __shared__ int   hqn;
    __shared__ float red[BLK];
    __shared__ int   s_exc, s_tot;

    int bid = blockIdx.x;
    int tid = threadIdx.x;
    int lane = tid & 31;
    int w = tid >> 5;

    // ---------- Phase A: load 4 elements/thread, per-block zero count ------
    int e0 = (bid * BLK + tid) * 4;
    int   lab[4];
    float sc[4];
    if (e0 + 3 < B) {
        int4   lv = __ldg((const int4*)(labels + e0));
        float4 sv = __ldg((const float4*)(scores + e0));
        lab[0] = lv.x; lab[1] = lv.y; lab[2] = lv.z; lab[3] = lv.w;
        sc[0] = sv.x; sc[1] = sv.y; sc[2] = sv.z; sc[3] = sv.w;
    } else {
#pragma unroll
        for (int k = 0; k < 4; k++) {
            lab[k] = (e0 + k < B) ? labels[e0 + k] : 1;
            sc[k]  = (e0 + k < B) ? scores[e0 + k] : 0.0f;
        }
    }
    int f[4], c = 0;
#pragma unroll
    for (int k = 0; k < 4; k++) { f[k] = (e0 + k < B && lab[k] == 0) ? 1 : 0; c += f[k]; }

    int incl = c;
#pragma unroll
    for (int off = 1; off < 32; off <<= 1) {
        int y = __shfl_up_sync(0xffffffffu, incl, off);
        if (lane >= off) incl += y;
    }
    int thr_exc = incl - c;
    if (lane == 31) wtot[w] = incl;
    __syncthreads();
    if (tid == 0) {
        int r = 0;
#pragma unroll
        for (int k = 0; k < BLK / 32; k++) { int t = wtot[k]; woff[k] = r; r += t; }
        g_blockcnt[bid] = r;
        hqn = 0;
        if (bid == 0) {
            g_extra = 0.0f;
            float h = 0.0f;
#pragma unroll
            for (int j = 1; j <= MAX_TRIALS; j++) {
                h += __fdiv_rn(1.0f, (float)j);
                g_harm[j - 1] = h;
            }
        }
    }
    grid.sync();

    // ---------- Phase B: block prefix + total, stable scatter --------------
    {
        int pref = 0, tot = 0;
        for (int j = tid; j < nb; j += BLK) {
            int v = g_blockcnt[j];
            tot += v;
            if (j < bid) pref += v;
        }
        redi[tid] = pref;
        redt[tid] = tot;
        __syncthreads();
        for (int off = BLK / 2; off > 0; off >>= 1) {
            if (tid < off) { redi[tid] += redi[tid + off]; redt[tid] += redt[tid + off]; }
            __syncthreads();
        }
        if (tid == 0) { s_exc = redi[0]; s_tot = redt[0]; }
        __syncthreads();

        int neg_before = s_exc + woff[w] + thr_exc;
#pragma unroll
        for (int k = 0; k < 4; k++) {
            int i = e0 + k;
            if (i < B) {
                if (f[k]) {
                    g_neg_score[neg_before] = sc[k];
                } else {
                    int ps = i - neg_before;
                    g_pos_idx[ps] = i;
                    g_pos_score[ps] = sc[k];
                }
            }
            neg_before += f[k];
        }
    }
    int num_neg = s_tot;
    int num_pos = B - num_neg;
    grid.sync();

    // ---------- Phase C: WARP loss -----------------------------------------
    float nnf = (float)num_neg;
    float acc = 0.0f;

    if (num_neg > 0) {
        int stride = gridDim.x * blockDim.x * 2;
        for (int base = (bid * blockDim.x + tid) * 2; base < num_pos;
             base += stride) {
            int cnt = min(2, num_pos - base);
            uint32_t jb[2];
            float ss[2];
            bool done[2];
#pragma unroll
            for (int k = 0; k < 2; k++) {
                if (k < cnt) {
                    int p = base + k;
                    jb[k] = (uint32_t)__ldg(&g_pos_idx[p]) * (uint32_t)MAX_TRIALS;
                    ss[k] = __ldg(&g_pos_score[p]);
                    done[k] = false;
                } else {
                    jb[k] = 0; ss[k] = 0.0f; done[k] = true;
                }
            }
            float ns0[2];
#pragma unroll
            for (int k = 0; k < 2; k++)
                if (!done[k]) ns0[k] = sample_neg(jb[k], nnf, num_neg);
#pragma unroll
            for (int k = 0; k < 2; k++) {
                if (!done[k] && ns0[k] + MARGIN > ss[k]) {
                    acc += __ldg(&g_harm[MAX_TRIALS - 1]) *
                           fmaxf(MARGIN - (ss[k] - ns0[k]), 0.0f);
                    done[k] = true;
                }
            }
            for (int t = 1; t < 9; t++) {
                bool any = false;
#pragma unroll
                for (int k = 0; k < 2; k++) any |= !done[k];
                if (!any) break;
#pragma unroll
                for (int k = 0; k < 2; k++) {
                    if (!done[k]) {
                        float ns = sample_neg(jb[k] + (uint32_t)t, nnf, num_neg);
                        if (ns + MARGIN > ss[k]) {
                            int rank = max(1, MAX_TRIALS / (t + 1));
                            acc += __ldg(&g_harm[rank - 1]) *
                                   fmaxf(MARGIN - (ss[k] - ns), 0.0f);
                            done[k] = true;
                        }
                    }
                }
            }
#pragma unroll
            for (int k = 0; k < 2; k++) {
                if (!done[k]) {
                    int h = atomicAdd(&hqn, 1);
                    if (h < 1024) hq[h] = base + k;
                }
            }
        }
    }
    __syncthreads();

    // heavy items: one warp per item, lanes = trials 9..40, then 41..49
    int nh = min(hqn, 1024);
    int wd = tid >> 5;
    int nw = BLK >> 5;
    for (int h = wd; h < nh; h += nw) {
        int p = hq[h];
        float s = __ldg(&g_pos_score[p]);
        uint32_t jb = (uint32_t)__ldg(&g_pos_idx[p]) * (uint32_t)MAX_TRIALS;

        int t1 = 9 + lane;
        float ns1 = sample_neg(jb + (uint32_t)t1, nnf, num_neg);
        unsigned m1 = __ballot_sync(0xffffffffu, ns1 + MARGIN > s);
        int hit_t = -1;
        float hit_ns = 0.0f;
        if (m1) {
            int lead = __ffs(m1) - 1;
            hit_t = 9 + lead;
            hit_ns = __shfl_sync(0xffffffffu, ns1, lead);
        } else {
            int t2 = 41 + lane;
            bool act = (t2 < MAX_TRIALS);
            float ns2 = act ? sample_neg(jb + (uint32_t)t2, nnf, num_neg) : 0.0f;
            unsigned m2 = __ballot_sync(0xffffffffu, act && (ns2 + MARGIN > s));
            if (m2) {
                int lead = __ffs(m2) - 1;
                hit_t = 41 + lead;
                hit_ns = __shfl_sync(0xffffffffu, ns2, lead);
            }
        }
        if (lane == 0 && hit_t >= 0) {
            int rank = max(1, MAX_TRIALS / (hit_t + 1));
            acc += __ldg(&g_harm[rank - 1]) * fmaxf(MARGIN - (s - hit_ns), 0.0f);
        }
    }

    red[tid] = acc;
    __syncthreads();
    for (int off = BLK / 2; off > 0; off >>= 1) {
        if (tid < off) red[tid] += red[tid + off];
        __syncthreads();
    }
    if (tid == 0 && red[0] != 0.0f) atomicAdd(&g_extra, red[0]);
    grid.sync();

    if (bid == 0 && tid == 0) {
        out[0] = (num_neg > 0 && num_pos > 0) ? g_extra / (float)num_pos : 0.0f;
    }
}

extern "C" void kernel_launch(void* const* d_in, const int* in_sizes, int n_in,
                              void* d_out, int out_size) {
    const int*   labels = (const int*)d_in[1];
    const float* scores = (const float*)d_in[0];
    float* out = (float*)d_out;
    int B  = in_sizes[0];
    int nb = (B + EPB - 1) / EPB;

    void* args[] = { (void*)&labels, (void*)&scores, (void*)&out,
                     (void*)&B, (void*)&nb };
    // re-order args to match kernel signature (labels, scores, out, B, nb)
    cudaLaunchCooperativeKernel((void*)everything_kernel,
                                dim3(nb), dim3(BLK), args, 0, 0);
}

// round 13
// speedup vs baseline: 1.4084x; 1.4084x over previous
#include <cuda_runtime.h>
#include <cstdint>

#define MARGIN 1.0f
#define MAX_TRIALS 50
#define BLK 256
#define MAIN_GRID 1184
#define MAX_B (1 << 20)
#define VEC_NB (MAX_B / (BLK * 4))         // 1024 chunk-counts (1024 elems each)

// Scratch (no allocations allowed in kernel_launch)
__device__ float g_neg_score[MAX_B];   // scores of label-0 examples, stable order
__device__ float g_pos_score[MAX_B];   // scores of label-1 examples, stable order
__device__ int   g_pos_idx[MAX_B];     // original indices of label-1 examples
__device__ int   g_blockcnt[VEC_NB];
__device__ int   g_num_neg;
__device__ int   g_done;
__device__ float g_extra;
__device__ float g_harm[MAX_TRIALS];

// ---------------- Threefry-2x32 (exact JAX partitionable semantics) --------
__device__ __forceinline__ uint32_t rotl32(uint32_t x, int d) {
    return __funnelshift_l(x, x, d);
}

__device__ __forceinline__ uint32_t jax_random_bits32(uint32_t j) {
    const uint32_t k0 = 0u, k1 = 42u;
    const uint32_t ks2 = k0 ^ k1 ^ 0x1BD11BDAu;
    uint32_t x0 = 0u + k0;          // c0 = hi32(j) = 0
    uint32_t x1 = j + k1;           // c1 = lo32(j)
    const int R0[4] = {13, 15, 26, 6};
    const int R1[4] = {17, 29, 16, 24};
#pragma unroll
    for (int i = 0; i < 4; i++) { x0 += x1; x1 = rotl32(x1, R0[i]); x1 ^= x0; }
    x0 += k1;  x1 += ks2 + 1u;
#pragma unroll
    for (int i = 0; i < 4; i++) { x0 += x1; x1 = rotl32(x1, R1[i]); x1 ^= x0; }
    x0 += ks2; x1 += k0 + 2u;
#pragma unroll
    for (int i = 0; i < 4; i++) { x0 += x1; x1 = rotl32(x1, R0[i]); x1 ^= x0; }
    x0 += k0;  x1 += k1 + 3u;
#pragma unroll
    for (int i = 0; i < 4; i++) { x0 += x1; x1 = rotl32(x1, R1[i]); x1 ^= x0; }
    x0 += k1;  x1 += ks2 + 4u;
#pragma unroll
    for (int i = 0; i < 4; i++) { x0 += x1; x1 = rotl32(x1, R0[i]); x1 ^= x0; }
    x0 += ks2; x1 += k0 + 5u;
    return x0 ^ x1;
}

__device__ __forceinline__ float bits_to_uniform(uint32_t bits) {
    return __uint_as_float((bits >> 9) | 0x3f800000u) - 1.0f;
}

__device__ __forceinline__ float sample_neg(uint32_t j, float nnf, int num_neg) {
    float u = bits_to_uniform(jax_random_bits32(j));
    int idx = (int)(u * nnf);
    idx = min(max(idx, 0), num_neg - 1);
    return __ldg(&g_neg_score[idx]);
}

__device__ __forceinline__ float warp_weight(int t) {
    int rank = max(1, MAX_TRIALS / (t + 1));
    return __ldg(&g_harm[rank - 1]);
}

// ---------------- Pass 1: MLP-8 count; one warp per 1024-elem chunk --------
// grid 128 x 256: each block covers 8 chunks (one per warp).
__global__ void count_zeros_kernel(const int* __restrict__ labels, int B) {
    int tid = threadIdx.x;
    int lane = tid & 31;
    int w = tid >> 5;
    int chunk = blockIdx.x * 8 + w;
    int base = chunk * 1024;
    int c = 0;
#pragma unroll
    for (int k = 0; k < 8; k++) {
        int e = base + (k * 32 + lane) * 4;
        if (e + 3 < B) {
            int4 lv = __ldg((const int4*)(labels + e));
            c += (lv.x == 0) + (lv.y == 0) + (lv.z == 0) + (lv.w == 0);
        } else {
            for (int q = 0; q < 4; q++)
                if (e + q < B && labels[e + q] == 0) c++;
        }
    }
#pragma unroll
    for (int off = 16; off > 0; off >>= 1)
        c += __shfl_down_sync(0xffffffffu, c, off);
    if (lane == 0) g_blockcnt[chunk] = c;
    if (blockIdx.x == 0 && tid == 0) {
        g_extra = 0.0f;
        float h = 0.0f;
#pragma unroll
        for (int j = 1; j <= MAX_TRIALS; j++) {
            h += __fdiv_rn(1.0f, (float)j);
            g_harm[j - 1] = h;
        }
    }
}

// ---------------- Pass 2: vec4 scatter with inline exclusive prefix --------
__global__ void scatter_kernel(const int* __restrict__ labels,
                               const float* __restrict__ scores, int B, int nb) {
    __shared__ int wtot[BLK / 32];
    __shared__ int redi[BLK];
    __shared__ int s_exc;
    __shared__ int woff[BLK / 32];
    int bid = blockIdx.x;
    int tid = threadIdx.x;
    int lane = tid & 31;
    int w = tid >> 5;
    int e0 = (bid * BLK + tid) * 4;

    int   lab[4];
    float sc[4];
    if (e0 + 3 < B) {
        int4   lv = __ldg((const int4*)(labels + e0));
        float4 sv = __ldg((const float4*)(scores + e0));
        lab[0] = lv.x; lab[1] = lv.y; lab[2] = lv.z; lab[3] = lv.w;
        sc[0] = sv.x; sc[1] = sv.y; sc[2] = sv.z; sc[3] = sv.w;
    } else {
        for (int k = 0; k < 4; k++) {
            lab[k] = (e0 + k < B) ? labels[e0 + k] : 1;
            sc[k]  = (e0 + k < B) ? scores[e0 + k] : 0.0f;
        }
    }
    int f[4], c = 0;
#pragma unroll
    for (int k = 0; k < 4; k++) { f[k] = (e0 + k < B && lab[k] == 0) ? 1 : 0; c += f[k]; }

    int incl = c;
#pragma unroll
    for (int off = 1; off < 32; off <<= 1) {
        int y = __shfl_up_sync(0xffffffffu, incl, off);
        if (lane >= off) incl += y;
    }
    int thr_exc = incl - c;
    if (lane == 31) wtot[w] = incl;

    int part = 0;
    for (int j = tid; j < bid; j += BLK) part += g_blockcnt[j];
    redi[tid] = part;
    __syncthreads();
    for (int off = BLK / 2; off > 0; off >>= 1) {
        if (tid < off) redi[tid] += redi[tid + off];
        __syncthreads();
    }
    if (tid == 0) {
        s_exc = redi[0];
        int r = 0;
#pragma unroll
        for (int k = 0; k < BLK / 32; k++) { int t = wtot[k]; woff[k] = r; r += t; }
        if (bid == nb - 1) g_num_neg = s_exc + r;
    }
    __syncthreads();

    int neg_before = s_exc + woff[w] + thr_exc;
#pragma unroll
    for (int k = 0; k < 4; k++) {
        int i = e0 + k;
        if (i < B) {
            if (f[k]) {
                g_neg_score[neg_before] = sc[k];
            } else {
                int ps = i - neg_before;
                g_pos_idx[ps] = i;
                g_pos_score[ps] = sc[k];
            }
        }
        neg_before += f[k];
    }
}

// ---------------- Main: trial-parallel loss + finalize ---------------------
__global__ __launch_bounds__(BLK) void main_kernel(float* __restrict__ out, int B) {
    __shared__ uint32_t q1_jb[1024];
    __shared__ float    q1_s[1024];
    __shared__ uint32_t q2_jb[1024];
    __shared__ float    q2_s[1024];
    __shared__ uint32_t q3_jb[256];
    __shared__ float    q3_s[256];
    __shared__ int q1n, q2n, q3n, take1, take2;
    __shared__ float red[BLK];
    __shared__ bool s_last;
    int tid = threadIdx.x;
    int lane = tid & 31;
    if (tid == 0) { q1n = 0; q2n = 0; q3n = 0; take1 = 0; take2 = 0; }
    __syncthreads();

    int num_neg = g_num_neg;
    int num_pos = B - num_neg;
    float nnf = (float)num_neg;
    float acc = 0.0f;

    // ---- Phase 1: trial 0 for every positive (uniform, no divergence) ----
    if (num_neg > 0) {
        int stride = gridDim.x * blockDim.x;
        for (int p = blockIdx.x * blockDim.x + tid; p < num_pos; p += stride) {
            uint32_t jb = (uint32_t)__ldg(&g_pos_idx[p]) * (uint32_t)MAX_TRIALS;
            float s = __ldg(&g_pos_score[p]);
            float ns = sample_neg(jb, nnf, num_neg);
            if (ns + MARGIN > s) {
                acc += __ldg(&g_harm[MAX_TRIALS - 1]) * fmaxf(MARGIN - (s - ns), 0.0f);
            } else {
                int h = atomicAdd(&q1n, 1);
                q1_jb[h] = jb; q1_s[h] = s;
            }
        }
    }
    __syncthreads();

    // ---- Phase 2: trials 1..4 — 8 survivors/warp, 4 lanes per survivor ----
    {
        int n1 = q1n;
        int sub = lane & 3;          // which trial within group
        int t = 1 + sub;
        while (true) {
            int b;
            if (lane == 0) b = atomicAdd(&take1, 8);
            b = __shfl_sync(0xffffffffu, b, 0);
            if (b >= n1) break;
            int nrem = n1 - b;
            int sid = lane >> 2;
            bool active = (sid < nrem);
            int qi = b + (active ? sid : 0);
            uint32_t jb = q1_jb[qi];
            float s = q1_s[qi];
            float ns = active ? sample_neg(jb + (uint32_t)t, nnf, num_neg) : 0.0f;
            bool viol = active && (ns + MARGIN > s);
            unsigned m = __ballot_sync(0xffffffffu, viol);
            unsigned nib = (m >> ((lane >> 2) * 4)) & 0xFu;
            if (viol && ((nib & ((1u << sub) - 1u)) == 0u)) {
                acc += warp_weight(t) * fmaxf(MARGIN - (s - ns), 0.0f);
            }
            if (active && sub == 0 && nib == 0u) {
                int h = atomicAdd(&q2n, 1);
                q2_jb[h] = jb; q2_s[h] = s;
            }
        }
    }
    __syncthreads();

    // ---- Phase 3: trials 5..8 — same pattern on q2, heavies -> q3 ---------
    {
        int n2 = q2n;
        int sub = lane & 3;
        int t = 5 + sub;
        while (true) {
            int b;
            if (lane == 0) b = atomicAdd(&take2, 8);
            b = __shfl_sync(0xffffffffu, b, 0);
            if (b >= n2) break;
            int nrem = n2 - b;
            int sid = lane >> 2;
            bool active = (sid < nrem);
            int qi = b + (active ? sid : 0);
            uint32_t jb = q2_jb[qi];
            float s = q2_s[qi];
            float ns = active ? sample_neg(jb + (uint32_t)t, nnf, num_neg) : 0.0f;
            bool viol = active && (ns + MARGIN > s);
            unsigned m = __ballot_sync(0xffffffffu, viol);
            unsigned nib = (m >> ((lane >> 2) * 4)) & 0xFu;
            if (viol && ((nib & ((1u << sub) - 1u)) == 0u)) {
                acc += warp_weight(t) * fmaxf(MARGIN - (s - ns), 0.0f);
            }
            if (active && sub == 0 && nib == 0u) {
                int h = atomicAdd(&q3n, 1);
                if (h < 256) { q3_jb[h] = jb; q3_s[h] = s; }
            }
        }
    }
    __syncthreads();

    // ---- Phase 4: heavies — one warp per item, lanes = trials 9..40/41..49
    {
        int n3 = min(q3n, 256);
        int wd = tid >> 5;
        int nw = BLK >> 5;
        for (int h = wd; h < n3; h += nw) {
            uint32_t jb = q3_jb[h];
            float s = q3_s[h];
            int t1 = 9 + lane;
            float ns1 = sample_neg(jb + (uint32_t)t1, nnf, num_neg);
            unsigned m1 = __ballot_sync(0xffffffffu, ns1 + MARGIN > s);
            int hit_t = -1;
            float hit_ns = 0.0f;
            if (m1) {
                int lead = __ffs(m1) - 1;
                hit_t = 9 + lead;
                hit_ns = __shfl_sync(0xffffffffu, ns1, lead);
            } else {
                int t2 = 41 + lane;
                bool act = (t2 < MAX_TRIALS);
                float ns2 = act ? sample_neg(jb + (uint32_t)t2, nnf, num_neg) : 0.0f;
                unsigned m2 = __ballot_sync(0xffffffffu, act && (ns2 + MARGIN > s));
                if (m2) {
                    int lead = __ffs(m2) - 1;
                    hit_t = 41 + lead;
                    hit_ns = __shfl_sync(0xffffffffu, ns2, lead);
                }
            }
            if (lane == 0 && hit_t >= 0) {
                acc += warp_weight(hit_t) * fmaxf(MARGIN - (s - hit_ns), 0.0f);
            }
        }
    }

    // ---- block reduction -> one global atomic; last block finalizes -------
    red[tid] = acc;
    __syncthreads();
    for (int off = BLK / 2; off > 0; off >>= 1) {
        if (tid < off) red[tid] += red[tid + off];
        __syncthreads();
    }
    if (tid == 0) {
        if (red[0] != 0.0f) atomicAdd(&g_extra, red[0]);
        __threadfence();
        int t = atomicAdd(&g_done, 1);
        s_last = (t == gridDim.x - 1);
    }
    __syncthreads();
    if (s_last && tid == 0) {
        out[0] = (num_neg > 0 && num_pos > 0) ? g_extra / (float)num_pos : 0.0f;
        g_done = 0;
    }
}

extern "C" void kernel_launch(void* const* d_in, const int* in_sizes, int n_in,
                              void* d_out, int out_size) {
    const float* scores = (const float*)d_in[0];
    const int*   labels = (const int*)d_in[1];
    float* out = (float*)d_out;
    int B  = in_sizes[0];
    int nb  = (B + BLK * 4 - 1) / (BLK * 4);       // 1024 scatter blocks / chunks
    int ncb = (nb + 7) / 8;                         // 128 count blocks

    count_zeros_kernel<<<ncb, BLK>>>(labels, B);
    scatter_kernel<<<nb, BLK>>>(labels, scores, B, nb);
    main_kernel<<<MAIN_GRID, BLK>>>(out, B);
}

// round 14
// speedup vs baseline: 1.5861x; 1.1262x over previous
#include <cuda_runtime.h>
#include <cstdint>

#define MARGIN 1.0f
#define MAX_TRIALS 50
#define BLK 256
#define CNT_BLK 128
#define MAIN_GRID 1184
#define MAX_B (1 << 20)
#define VEC_NB (MAX_B / (BLK * 4))         // 1024 chunk-counts (1024 elems each)

// Scratch (no allocations allowed in kernel_launch)
__device__ float g_neg_score[MAX_B];   // scores of label-0 examples, stable order
__device__ float g_pos_score[MAX_B];   // scores of label-1 examples, stable order
__device__ int   g_pos_idx[MAX_B];     // original indices of label-1 examples
__device__ int   g_blockcnt[VEC_NB];
__device__ int   g_num_neg;
__device__ int   g_done;
__device__ float g_extra;
__device__ float g_harm[MAX_TRIALS];

// ---------------- Threefry-2x32 (exact JAX partitionable semantics) --------
__device__ __forceinline__ uint32_t rotl32(uint32_t x, int d) {
    return __funnelshift_l(x, x, d);
}

__device__ __forceinline__ uint32_t jax_random_bits32(uint32_t j) {
    const uint32_t k0 = 0u, k1 = 42u;
    const uint32_t ks2 = k0 ^ k1 ^ 0x1BD11BDAu;
    uint32_t x0 = 0u + k0;          // c0 = hi32(j) = 0
    uint32_t x1 = j + k1;           // c1 = lo32(j)
    const int R0[4] = {13, 15, 26, 6};
    const int R1[4] = {17, 29, 16, 24};
#pragma unroll
    for (int i = 0; i < 4; i++) { x0 += x1; x1 = rotl32(x1, R0[i]); x1 ^= x0; }
    x0 += k1;  x1 += ks2 + 1u;
#pragma unroll
    for (int i = 0; i < 4; i++) { x0 += x1; x1 = rotl32(x1, R1[i]); x1 ^= x0; }
    x0 += ks2; x1 += k0 + 2u;
#pragma unroll
    for (int i = 0; i < 4; i++) { x0 += x1; x1 = rotl32(x1, R0[i]); x1 ^= x0; }
    x0 += k0;  x1 += k1 + 3u;
#pragma unroll
    for (int i = 0; i < 4; i++) { x0 += x1; x1 = rotl32(x1, R1[i]); x1 ^= x0; }
    x0 += k1;  x1 += ks2 + 4u;
#pragma unroll
    for (int i = 0; i < 4; i++) { x0 += x1; x1 = rotl32(x1, R0[i]); x1 ^= x0; }
    x0 += ks2; x1 += k0 + 5u;
    return x0 ^ x1;
}

__device__ __forceinline__ float bits_to_uniform(uint32_t bits) {
    return __uint_as_float((bits >> 9) | 0x3f800000u) - 1.0f;
}

__device__ __forceinline__ float sample_neg(uint32_t j, float nnf, int num_neg) {
    float u = bits_to_uniform(jax_random_bits32(j));
    int idx = (int)(u * nnf);
    idx = min(max(idx, 0), num_neg - 1);
    return __ldg(&g_neg_score[idx]);
}

__device__ __forceinline__ float warp_weight(int t) {
    int rank = max(1, MAX_TRIALS / (t + 1));
    return __ldg(&g_harm[rank - 1]);
}

// ---------------- Pass 1: count; 1024 blocks x 128 thr, 2x int4/thread -----
// Each block owns one 1024-elem chunk: MLP-2 per thread + high TLP.
__global__ void count_zeros_kernel(const int* __restrict__ labels, int B) {
    int tid = threadIdx.x;
    int base = blockIdx.x * 1024;
    int c = 0;
    int e1 = base + tid * 4;
    int e2 = base + 512 + tid * 4;
    if (e2 + 3 < B) {
        int4 a = __ldg((const int4*)(labels + e1));
        int4 b = __ldg((const int4*)(labels + e2));
        c  = (a.x == 0) + (a.y == 0) + (a.z == 0) + (a.w == 0);
        c += (b.x == 0) + (b.y == 0) + (b.z == 0) + (b.w == 0);
    } else {
        for (int q = 0; q < 4; q++) {
            if (e1 + q < B && labels[e1 + q] == 0) c++;
            if (e2 + q < B && labels[e2 + q] == 0) c++;
        }
    }
#pragma unroll
    for (int off = 16; off > 0; off >>= 1)
        c += __shfl_down_sync(0xffffffffu, c, off);
    __shared__ int wsum[CNT_BLK / 32];
    if ((tid & 31) == 0) wsum[tid >> 5] = c;
    __syncthreads();
    if (tid == 0) {
        int s = 0;
#pragma unroll
        for (int w = 0; w < CNT_BLK / 32; w++) s += wsum[w];
        g_blockcnt[blockIdx.x] = s;
        if (blockIdx.x == 0) {
            g_extra = 0.0f;
            float h = 0.0f;
#pragma unroll
            for (int j = 1; j <= MAX_TRIALS; j++) {
                h += __fdiv_rn(1.0f, (float)j);
                g_harm[j - 1] = h;
            }
        }
    }
}

// ---------------- Pass 2: vec4 scatter with inline exclusive prefix --------
__global__ void scatter_kernel(const int* __restrict__ labels,
                               const float* __restrict__ scores, int B, int nb) {
    __shared__ int wtot[BLK / 32];
    __shared__ int redi[BLK];
    __shared__ int s_exc;
    __shared__ int woff[BLK / 32];
    int bid = blockIdx.x;
    int tid = threadIdx.x;
    int lane = tid & 31;
    int w = tid >> 5;
    int e0 = (bid * BLK + tid) * 4;

    int   lab[4];
    float sc[4];
    if (e0 + 3 < B) {
        int4   lv = __ldg((const int4*)(labels + e0));
        float4 sv = __ldg((const float4*)(scores + e0));
        lab[0] = lv.x; lab[1] = lv.y; lab[2] = lv.z; lab[3] = lv.w;
        sc[0] = sv.x; sc[1] = sv.y; sc[2] = sv.z; sc[3] = sv.w;
    } else {
        for (int k = 0; k < 4; k++) {
            lab[k] = (e0 + k < B) ? labels[e0 + k] : 1;
            sc[k]  = (e0 + k < B) ? scores[e0 + k] : 0.0f;
        }
    }
    int f[4], c = 0;
#pragma unroll
    for (int k = 0; k < 4; k++) { f[k] = (e0 + k < B && lab[k] == 0) ? 1 : 0; c += f[k]; }

    int incl = c;
#pragma unroll
    for (int off = 1; off < 32; off <<= 1) {
        int y = __shfl_up_sync(0xffffffffu, incl, off);
        if (lane >= off) incl += y;
    }
    int thr_exc = incl - c;
    if (lane == 31) wtot[w] = incl;

    int part = 0;
    for (int j = tid; j < bid; j += BLK) part += g_blockcnt[j];
    redi[tid] = part;
    __syncthreads();
    for (int off = BLK / 2; off > 0; off >>= 1) {
        if (tid < off) redi[tid] += redi[tid + off];
        __syncthreads();
    }
    if (tid == 0) {
        s_exc = redi[0];
        int r = 0;
#pragma unroll
        for (int k = 0; k < BLK / 32; k++) { int t = wtot[k]; woff[k] = r; r += t; }
        if (bid == nb - 1) g_num_neg = s_exc + r;
    }
    __syncthreads();

    int neg_before = s_exc + woff[w] + thr_exc;
#pragma unroll
    for (int k = 0; k < 4; k++) {
        int i = e0 + k;
        if (i < B) {
            if (f[k]) {
                g_neg_score[neg_before] = sc[k];
            } else {
                int ps = i - neg_before;
                g_pos_idx[ps] = i;
                g_pos_score[ps] = sc[k];
            }
        }
        neg_before += f[k];
    }
}

// ---------------- Main: trial-parallel loss + finalize ---------------------
__global__ __launch_bounds__(BLK) void main_kernel(float* __restrict__ out, int B) {
    __shared__ uint32_t q1_jb[1024];
    __shared__ float    q1_s[1024];
    __shared__ uint32_t q2_jb[1024];
    __shared__ float    q2_s[1024];
    __shared__ uint32_t q3_jb[256];
    __shared__ float    q3_s[256];
    __shared__ int q1n, q2n, q3n, take1, take2;
    __shared__ float red[BLK];
    __shared__ bool s_last;
    int tid = threadIdx.x;
    int lane = tid & 31;
    if (tid == 0) { q1n = 0; q2n = 0; q3n = 0; take1 = 0; take2 = 0; }
    __syncthreads();

    int num_neg = g_num_neg;
    int num_pos = B - num_neg;
    float nnf = (float)num_neg;
    float acc = 0.0f;

    // ---- Phase 1: trial 0 for every positive (uniform, no divergence) ----
    if (num_neg > 0) {
        int stride = gridDim.x * blockDim.x;
        for (int p = blockIdx.x * blockDim.x + tid; p < num_pos; p += stride) {
            uint32_t jb = (uint32_t)__ldg(&g_pos_idx[p]) * (uint32_t)MAX_TRIALS;
            float s = __ldg(&g_pos_score[p]);
            float ns = sample_neg(jb, nnf, num_neg);
            if (ns + MARGIN > s) {
                acc += __ldg(&g_harm[MAX_TRIALS - 1]) * fmaxf(MARGIN - (s - ns), 0.0f);
            } else {
                int h = atomicAdd(&q1n, 1);
                q1_jb[h] = jb; q1_s[h] = s;
            }
        }
    }
    __syncthreads();

    // ---- Phase 2: trials 1..4 — 8 survivors/warp, 4 lanes per survivor ----
    {
        int n1 = q1n;
        int sub = lane & 3;          // which trial within group
        int t = 1 + sub;
        while (true) {
            int b;
            if (lane == 0) b = atomicAdd(&take1, 8);
            b = __shfl_sync(0xffffffffu, b, 0);
            if (b >= n1) break;
            int nrem = n1 - b;
            int sid = lane >> 2;
            bool active = (sid < nrem);
            int qi = b + (active ? sid : 0);
            uint32_t jb = q1_jb[qi];
            float s = q1_s[qi];
            float ns = active ? sample_neg(jb + (uint32_t)t, nnf, num_neg) : 0.0f;
            bool viol = active && (ns + MARGIN > s);
            unsigned m = __ballot_sync(0xffffffffu, viol);
            unsigned nib = (m >> ((lane >> 2) * 4)) & 0xFu;
            if (viol && ((nib & ((1u << sub) - 1u)) == 0u)) {
                acc += warp_weight(t) * fmaxf(MARGIN - (s - ns), 0.0f);
            }
            if (active && sub == 0 && nib == 0u) {
                int h = atomicAdd(&q2n, 1);
                q2_jb[h] = jb; q2_s[h] = s;
            }
        }
    }
    __syncthreads();

    // ---- Phase 3: trials 5..8 — same pattern on q2, heavies -> q3 ---------
    {
        int n2 = q2n;
        int sub = lane & 3;
        int t = 5 + sub;
        while (true) {
            int b;
            if (lane == 0) b = atomicAdd(&take2, 8);
            b = __shfl_sync(0xffffffffu, b, 0);
            if (b >= n2) break;
            int nrem = n2 - b;
            int sid = lane >> 2;
            bool active = (sid < nrem);
            int qi = b + (active ? sid : 0);
            uint32_t jb = q2_jb[qi];
            float s = q2_s[qi];
            float ns = active ? sample_neg(jb + (uint32_t)t, nnf, num_neg) : 0.0f;
            bool viol = active && (ns + MARGIN > s);
            unsigned m = __ballot_sync(0xffffffffu, viol);
            unsigned nib = (m >> ((lane >> 2) * 4)) & 0xFu;
            if (viol && ((nib & ((1u << sub) - 1u)) == 0u)) {
                acc += warp_weight(t) * fmaxf(MARGIN - (s - ns), 0.0f);
            }
            if (active && sub == 0 && nib == 0u) {
                int h = atomicAdd(&q3n, 1);
                if (h < 256) { q3_jb[h] = jb; q3_s[h] = s; }
            }
        }
    }
    __syncthreads();

    // ---- Phase 4: heavies — one warp per item, lanes = trials 9..40/41..49
    {
        int n3 = min(q3n, 256);
        int wd = tid >> 5;
        int nw = BLK >> 5;
        for (int h = wd; h < n3; h += nw) {
            uint32_t jb = q3_jb[h];
            float s = q3_s[h];
            int t1 = 9 + lane;
            float ns1 = sample_neg(jb + (uint32_t)t1, nnf, num_neg);
            unsigned m1 = __ballot_sync(0xffffffffu, ns1 + MARGIN > s);
            int hit_t = -1;
            float hit_ns = 0.0f;
            if (m1) {
                int lead = __ffs(m1) - 1;
                hit_t = 9 + lead;
                hit_ns = __shfl_sync(0xffffffffu, ns1, lead);
            } else {
                int t2 = 41 + lane;
                bool act = (t2 < MAX_TRIALS);
                float ns2 = act ? sample_neg(jb + (uint32_t)t2, nnf, num_neg) : 0.0f;
                unsigned m2 = __ballot_sync(0xffffffffu, act && (ns2 + MARGIN > s));
                if (m2) {
                    int lead = __ffs(m2) - 1;
                    hit_t = 41 + lead;
                    hit_ns = __shfl_sync(0xffffffffu, ns2, lead);
                }
            }
            if (lane == 0 && hit_t >= 0) {
                acc += warp_weight(hit_t) * fmaxf(MARGIN - (s - hit_ns), 0.0f);
            }
        }
    }

    // ---- block reduction -> one global atomic; last block finalizes -------
    red[tid] = acc;
    __syncthreads();
    for (int off = BLK / 2; off > 0; off >>= 1) {
        if (tid < off) red[tid] += red[tid + off];
        __syncthreads();
    }
    if (tid == 0) {
        if (red[0] != 0.0f) atomicAdd(&g_extra, red[0]);
        __threadfence();
        int t = atomicAdd(&g_done, 1);
        s_last = (t == gridDim.x - 1);
    }
    __syncthreads();
    if (s_last && tid == 0) {
        out[0] = (num_neg > 0 && num_pos > 0) ? g_extra / (float)num_pos : 0.0f;
        g_done = 0;
    }
}

extern "C" void kernel_launch(void* const* d_in, const int* in_sizes, int n_in,
                              void* d_out, int out_size) {
    const float* scores = (const float*)d_in[0];
    const int*   labels = (const int*)d_in[1];
    float* out = (float*)d_out;
    int B  = in_sizes[0];
    int nb = (B + BLK * 4 - 1) / (BLK * 4);       // 1024 scatter blocks / chunks

    count_zeros_kernel<<<nb, CNT_BLK>>>(labels, B);
    scatter_kernel<<<nb, BLK>>>(labels, scores, B, nb);
    main_kernel<<<MAIN_GRID, BLK>>>(out, B);
}